// round 7
// baseline (speedup 1.0000x reference)
#include <cuda_runtime.h>
#include <math.h>

#define KSTEPS 512
#define BATCH  64
#define NSTATE 128
#define NINPUT 32
#define HIDDEN 256
#define FIN    161

// SMEM layout (float offsets)
#define OFF_W2Q 0          // 32768: w2q[j4*128+i] = float4 W2[i][4j4..] as ulonglong2
#define OFF_MSM 32768      // 22528: Msm_u64[m2*512 + t], m2 in [0,22)  (M tail, per-thread column)
#define OFF_TS  55296      // 512:   T double buffer (2 x 256)
#define OFF_TBS 55808      // 256:   Tb = sum b_j T_j
#define OFF_KP  56064      // 512:   W2 quarter partials
#define OFF_TSS 56576      // 512:   time grid
#define SMEM_FLOATS 57088
#define SMEM_BYTES  (SMEM_FLOATS * 4)   // 228352 B < 227KB opt-in limit

__device__ __align__(16) float g_M[HIDDEN * HIDDEN];          // M = W1y @ W2
__device__ float g_c[HIDDEN];                                  // c = W1y @ b2
__device__ float g_P[(size_t)BATCH * KSTEPS * HIDDEN];         // P[b][i][r] = Wu @ u_i

__device__ __forceinline__ unsigned long long ffma2(unsigned long long a,
                                                    unsigned long long b,
                                                    unsigned long long c) {
    unsigned long long d;
    asm("fma.rn.f32x2 %0, %1, %2, %3;" : "=l"(d) : "l"(a), "l"(b), "l"(c));
    return d;
}
__device__ __forceinline__ float lo32(unsigned long long v) { return __uint_as_float((unsigned)v); }
__device__ __forceinline__ float hi32(unsigned long long v) { return __uint_as_float((unsigned)(v >> 32)); }
__device__ __forceinline__ unsigned long long pack2(float a, float b) {
    return (unsigned long long)__float_as_uint(a) | ((unsigned long long)__float_as_uint(b) << 32);
}
__device__ __forceinline__ float tanh_fast(float x) {
    float y;
    asm("tanh.approx.f32 %0, %1;" : "=f"(y) : "f"(x));
    return y;
}

// ---------------- precompute M = W1[:,1:129] @ W2, c = W1[:,1:129] @ b2 ----------------
__global__ void precompute_M(const float* __restrict__ W1,
                             const float* __restrict__ W2,
                             const float* __restrict__ b2)
{
    __shared__ float w1row[FIN];
    const int r = blockIdx.x;
    const int k = threadIdx.x;
    for (int j = k; j < FIN; j += blockDim.x) w1row[j] = W1[r * FIN + j];
    __syncthreads();
    float acc = 0.f;
#pragma unroll 8
    for (int i = 0; i < NSTATE; i++)
        acc = fmaf(w1row[1 + i], __ldg(&W2[i * HIDDEN + k]), acc);
    g_M[r * HIDDEN + k] = acc;
    if (k == 0) {
        float c = 0.f;
        for (int i = 0; i < NSTATE; i++) c = fmaf(w1row[1 + i], __ldg(&b2[i]), c);
        g_c[r] = c;
    }
}

// ---------------- precompute P[b][i][r] = Wu[r,:] . us[b][i][:] ----------------
__global__ void precompute_P(const float* __restrict__ W1,
                             const float* __restrict__ us)
{
    __shared__ float ush[64 * NINPUT];
    const int b = blockIdx.x;
    const int i0 = blockIdx.y * 64;
    const int r = threadIdx.x;
    float wu[NINPUT];
#pragma unroll
    for (int j = 0; j < NINPUT; j++) wu[j] = __ldg(&W1[r * FIN + 129 + j]);
    for (int idx = r; idx < 64 * NINPUT; idx += 256)
        ush[idx] = us[((size_t)b * KSTEPS + i0) * NINPUT + idx];
    __syncthreads();
    for (int ii = 0; ii < 64; ii++) {
        float acc = 0.f;
#pragma unroll
        for (int j = 0; j < NINPUT; j++) acc = fmaf(wu[j], ush[ii * NINPUT + j], acc);
        g_P[((size_t)b * KSTEPS + i0 + ii) * HIDDEN + r] = acc;
    }
}

// ---------------- main solver ----------------
__global__ __launch_bounds__(512, 1)
void ode_tsit5_kernel(const float* __restrict__ ts,
                      const float* __restrict__ y0,
                      const float* __restrict__ W1,
                      const float* __restrict__ b1,
                      const float* __restrict__ W2,
                      const float* __restrict__ b2,
                      float* __restrict__ out)
{
    const float TH[6] = {0.0f, 0.161f, 0.327f, 0.9f, 0.9800255409045097f, 1.0f};
    const float A[5][5] = {
        {0.161f, 0.f, 0.f, 0.f, 0.f},
        {-0.008480655492356989f, 0.335480655492357f, 0.f, 0.f, 0.f},
        {2.8971530571054935f, -6.359448489975075f, 4.3622954328695815f, 0.f, 0.f},
        {5.325864828439257f, -11.748883564062828f, 7.4955393428898365f, -0.09249506636175525f, 0.f},
        {5.86145544294642f, -12.92096931784711f, 8.159367898576159f, -0.071584973281401f, -0.028269050394068383f}
    };
    const float Bw[6] = {0.09646076681806523f, 0.01f, 0.4798896504144996f,
                         1.379008574103742f, -3.290069515436081f, 2.324710524099774f};

    extern __shared__ float sm[];
    float* Ts   = sm + OFF_TS;
    float* Tbs  = sm + OFF_TBS;
    float* kp   = sm + OFF_KP;
    float* tss  = sm + OFF_TSS;
    ulonglong2* w2q = (ulonglong2*)(sm + OFF_W2Q);
    unsigned long long* Msm = (unsigned long long*)(sm + OFF_MSM);

    const int b = blockIdx.x;
    const int t = threadIdx.x;
    const int r = t >> 1;            // pre-activation row 0..255
    const int p = t & 1;             // half of the 256 k-dim
    const int i = t & 127;           // W2-phase output index
    const int q = (t >> 7) & 3;      // W2-phase quarter

    // ---- M: 84 elems/thread in registers, 44 via smem (per-thread column layout) ----
    unsigned long long mreg[42];
    {
        const unsigned long long* gm =
            (const unsigned long long*)&g_M[r * HIDDEN + p * 128];
#pragma unroll
        for (int m = 0; m < 42; m++) mreg[m] = gm[m];
        const unsigned long long* gt =
            (const unsigned long long*)&g_M[r * HIDDEN + p * 128 + 84];
#pragma unroll
        for (int m2 = 0; m2 < 22; m2++)
            Msm[m2 * 512 + t] = gt[m2];
    }
    const float creg = g_c[r];
    const float w1t  = __ldg(&W1[r * FIN]);
    const float b2r  = (t < 128) ? __ldg(&b2[t]) : 0.0f;

    // ---- W2 packed float4-in-j: w2q[j4*128 + ii] = W2[ii][4j4..4j4+3] ----
    {
        const float4* W2v = (const float4*)W2;
        for (int idx = t; idx < NSTATE * HIDDEN / 4; idx += 512) {
            int ii = idx >> 6, j4 = idx & 63;
            float4 w = W2v[ii * 64 + j4];
            ulonglong2 pk; pk.x = pack2(w.x, w.y); pk.y = pack2(w.z, w.w);
            w2q[j4 * 128 + ii] = pk;
        }
    }
    if (t < KSTEPS) tss[t] = ts[t];

    // ---- beta = W1y . y0 + b1 (pair-split dot) ----
    float beta;
    {
        const float* w1p = W1 + r * FIN + 1 + p * 64;
        const float* yp  = y0 + b * NSTATE + p * 64;
        float acc = 0.f;
#pragma unroll 8
        for (int ii = 0; ii < 64; ii++) acc = fmaf(__ldg(&w1p[ii]), __ldg(&yp[ii]), acc);
        acc += __shfl_xor_sync(0xFFFFFFFFu, acc, 1);
        beta = acc + __ldg(&b1[r]);
    }

    // ---- y output state ----
    float yreg = 0.f;
    if (t < NSTATE) {
        yreg = y0[b * NSTATE + t];
        out[(size_t)b * KSTEPS * NSTATE + t] = yreg;
    }

    // ---- P projections (precomputed); Q derived on the fly ----
    const float* gPb = g_P + (size_t)b * KSTEPS * HIDDEN + r;
    float P0    = __ldg(&gPb[0]);
    float P1    = __ldg(&gPb[HIDDEN]);
    float Pnext = __ldg(&gPb[2 * HIDDEN]);

    __syncthreads();

    float Q1 = __fdividef(P1 - P0, tss[1] - tss[0]);
    float Q0 = Q1;
    float act = fmaf(w1t, tss[0], beta + P0);
    float Garr[5];

    for (int step = 0; step < KSTEPS - 1; ++step) {
        const float t0   = tss[step];
        const float hcur = tss[step + 1] - t0;
        float Tbacc = 0.f, bGacc = 0.f;

#pragma unroll
        for (int s = 0; s < 6; s++) {
            float* Tsb = Ts + (s & 1) * 256;
            float T = tanh_fast(act);
            Tbacc = fmaf(Bw[s], T, Tbacc);
            if (p == 0) Tsb[r] = T;
            __syncthreads();
            // ---- G = M . T + c ----
            float G;
            {
                const ulonglong2* Tq = (const ulonglong2*)(Tsb + p * 128);
                unsigned long long a0 = 0ull, a1 = 0ull, a2 = 0ull, a3 = 0ull;
#pragma unroll
                for (int m = 0; m < 10; m++) {
                    ulonglong2 z0 = Tq[2 * m], z1 = Tq[2 * m + 1];
                    a0 = ffma2(mreg[4 * m + 0], z0.x, a0);
                    a1 = ffma2(mreg[4 * m + 1], z0.y, a1);
                    a2 = ffma2(mreg[4 * m + 2], z1.x, a2);
                    a3 = ffma2(mreg[4 * m + 3], z1.y, a3);
                }
                { ulonglong2 z0 = Tq[20];
                  a0 = ffma2(mreg[40], z0.x, a0);
                  a1 = ffma2(mreg[41], z0.y, a1); }
                const ulonglong2* Tq2 = (const ulonglong2*)(Tsb + p * 128 + 84);
                const unsigned long long* Mp = Msm + t;
#pragma unroll
                for (int m = 0; m < 11; m++) {
                    ulonglong2 z = Tq2[m];
                    a2 = ffma2(Mp[(2 * m) * 512],     z.x, a2);
                    a3 = ffma2(Mp[(2 * m + 1) * 512], z.y, a3);
                }
                float half = (lo32(a0) + hi32(a0)) + (lo32(a1) + hi32(a1))
                           + (lo32(a2) + hi32(a2)) + (lo32(a3) + hi32(a3));
                half += __shfl_xor_sync(0xFFFFFFFFu, half, 1);
                G = half + creg;
            }
            bGacc = fmaf(Bw[s], G, bGacc);
            if (s < 5) {
                Garr[s] = G;
                float th = TH[s + 1];
                float t2 = th * th, t3 = t2 * th;
                float h00 = 2.f * t3 - 3.f * t2 + 1.f;
                float h01 = -2.f * t3 + 3.f * t2;
                float h10 = t3 - 2.f * t2 + th;
                float h11 = t3 - t2;
                float herm = h00 * P0 + h01 * P1 + hcur * (h10 * Q0 + h11 * Q1);
                float asum = 0.f;
#pragma unroll
                for (int j = 0; j <= s; j++) asum = fmaf(A[s][j], Garr[j], asum);
                act = fmaf(w1t, fmaf(th, hcur, t0), beta + herm + hcur * asum);
            }
        }

        // ---- step-end: publish Tb ----
        if (p == 0) Tbs[r] = Tbacc;
        __syncthreads();

        // ---- W2 . Tb quarter-dot ----
        {
            const ulonglong2* hq = (const ulonglong2*)(Tbs + q * 64);
            const ulonglong2* wp = w2q + q * 16 * 128 + i;
            unsigned long long a0 = 0ull, a1 = 0ull, a2 = 0ull, a3 = 0ull;
#pragma unroll
            for (int m = 0; m < 8; m++) {
                ulonglong2 w0 = wp[(2 * m) * 128];     ulonglong2 h0 = hq[2 * m];
                a0 = ffma2(w0.x, h0.x, a0);            a1 = ffma2(w0.y, h0.y, a1);
                ulonglong2 w1 = wp[(2 * m + 1) * 128]; ulonglong2 h1 = hq[2 * m + 1];
                a2 = ffma2(w1.x, h1.x, a2);            a3 = ffma2(w1.y, h1.y, a3);
            }
            kp[q * 128 + i] = (lo32(a0) + hi32(a0)) + (lo32(a1) + hi32(a1))
                            + (lo32(a2) + hi32(a2)) + (lo32(a3) + hi32(a3));
        }
        __syncthreads();

        // ---- finalize: y output, beta/P/Q rotate, next act0 ----
        if (t < 128) {
            float kv = (kp[i] + kp[128 + i]) + (kp[256 + i] + kp[384 + i]);
            yreg = fmaf(hcur, kv + b2r, yreg);     // sum(Bw) == 1
            out[((size_t)b * KSTEPS + step + 1) * NSTATE + i] = yreg;
        }
        beta = fmaf(hcur, bGacc, beta);
        P0 = P1; Q0 = Q1; P1 = Pnext;
        if (step + 2 < KSTEPS) {
            Q1 = __fdividef(P1 - P0, tss[step + 2] - tss[step + 1]);
            if (step + 3 < KSTEPS) Pnext = __ldg(&gPb[(size_t)(step + 3) * HIDDEN]);
        } else {
            Q1 = 0.f;
        }
        act = fmaf(w1t, tss[step + 1], beta + P0);
    }
}

extern "C" void kernel_launch(void* const* d_in, const int* in_sizes, int n_in,
                              void* d_out, int out_size)
{
    const float *ts = nullptr, *y0 = nullptr, *us = nullptr;
    const float *W1 = nullptr, *b1 = nullptr, *W2 = nullptr, *b2 = nullptr;
    for (int i = 0; i < n_in; i++) {
        switch (in_sizes[i]) {
            case 512:      ts = (const float*)d_in[i]; break;
            case 8192:     y0 = (const float*)d_in[i]; break;
            case 1048576:  us = (const float*)d_in[i]; break;
            case 41216:    W1 = (const float*)d_in[i]; break;
            case 256:      b1 = (const float*)d_in[i]; break;
            case 32768:    W2 = (const float*)d_in[i]; break;
            case 128:      b2 = (const float*)d_in[i]; break;
            default: break;
        }
    }
    float* out = (float*)d_out;

    precompute_M<<<HIDDEN, HIDDEN>>>(W1, W2, b2);
    {
        dim3 g(BATCH, KSTEPS / 64);
        precompute_P<<<g, 256>>>(W1, us);
    }
    cudaFuncSetAttribute(ode_tsit5_kernel,
                         cudaFuncAttributeMaxDynamicSharedMemorySize, SMEM_BYTES);
    ode_tsit5_kernel<<<BATCH, 512, SMEM_BYTES>>>(ts, y0, W1, b1, W2, b2, out);
}

// round 8
// speedup vs baseline: 1.3731x; 1.3731x over previous
#include <cuda_runtime.h>
#include <cstdint>
#include <math.h>

#define KSTEPS 512
#define BATCH  64
#define NSTATE 128
#define NINPUT 32
#define HIDDEN 256
#define FIN    161

// SMEM float offsets (per CTA)
#define OFF_W2  0        // 16384: this CTA's 64 W2 rows, packed k-major ulonglong2
#define OFF_TP0 16384    // 288: T buffer 0 (4 sections x 72, padded)
#define OFF_TP1 16672    // 288: T buffer 1
#define OFF_TB  16960    // 256: Tb (full)
#define OFF_KP  17216    // 512: W2 partials
#define OFF_TSS 17728    // 512: time grid
#define OFF_MB  18240    // 4:   mbarrier (16B aligned)
#define SMEM_FLOATS 18244
#define SMEM_BYTES  (SMEM_FLOATS * 4)

__device__ __align__(16) float g_M[HIDDEN * HIDDEN];          // M = W1y @ W2
__device__ float g_c[HIDDEN];                                  // c = W1y @ b2
__device__ float g_P[(size_t)BATCH * KSTEPS * HIDDEN];         // P[b][i][r] = Wu @ u_i

__device__ __forceinline__ unsigned long long ffma2(unsigned long long a,
                                                    unsigned long long b,
                                                    unsigned long long c) {
    unsigned long long d;
    asm("fma.rn.f32x2 %0, %1, %2, %3;" : "=l"(d) : "l"(a), "l"(b), "l"(c));
    return d;
}
__device__ __forceinline__ float lo32(unsigned long long v) { return __uint_as_float((unsigned)v); }
__device__ __forceinline__ float hi32(unsigned long long v) { return __uint_as_float((unsigned)(v >> 32)); }
__device__ __forceinline__ unsigned long long pack2(float a, float b) {
    return (unsigned long long)__float_as_uint(a) | ((unsigned long long)__float_as_uint(b) << 32);
}
__device__ __forceinline__ float tanh_fast(float x) {
    float y;
    asm("tanh.approx.f32 %0, %1;" : "=f"(y) : "f"(x));
    return y;
}
__device__ __forceinline__ uint32_t smem_u32(const void* p) {
    uint32_t a;
    asm("{ .reg .u64 tmp; cvta.to.shared.u64 tmp, %1; cvt.u32.u64 %0, tmp; }"
        : "=r"(a) : "l"(p));
    return a;
}
__device__ __forceinline__ uint32_t mapa_u32(uint32_t addr, uint32_t rank) {
    uint32_t r;
    asm("mapa.shared::cluster.u32 %0, %1, %2;" : "=r"(r) : "r"(addr), "r"(rank));
    return r;
}
__device__ __forceinline__ void st_cluster_f32(uint32_t addr, float v) {
    asm volatile("st.shared::cluster.f32 [%0], %1;" :: "r"(addr), "f"(v) : "memory");
}

// exchange: local writes done -> CTA sync -> release-arrive on peer -> wait local parity -> acquire
#define XCHG_SIGNAL_WAIT()                                                      \
    __syncthreads();                                                            \
    if (t == 0) {                                                               \
        asm volatile("fence.acq_rel.cluster;" ::: "memory");                    \
        asm volatile("mbarrier.arrive.shared::cluster.b64 _, [%0];"             \
                     :: "r"(mb_remote) : "memory");                             \
    }                                                                           \
    {                                                                           \
        uint32_t _done;                                                         \
        asm volatile("{\n\t.reg .pred p;\n\t"                                   \
            "mbarrier.try_wait.parity.acquire.cta.shared::cta.b64 p, [%1], %2;\n\t" \
            "selp.b32 %0, 1, 0, p;\n\t}"                                        \
            : "=r"(_done) : "r"(mb_local), "r"(xph) : "memory");                \
        while (!_done) {                                                        \
            asm volatile("{\n\t.reg .pred p;\n\t"                               \
                "mbarrier.try_wait.parity.acquire.cta.shared::cta.b64 p, [%1], %2, 0x989680;\n\t" \
                "selp.b32 %0, 1, 0, p;\n\t}"                                    \
                : "=r"(_done) : "r"(mb_local), "r"(xph) : "memory");            \
        }                                                                       \
        xph ^= 1;                                                               \
        asm volatile("fence.acq_rel.cluster;" ::: "memory");                    \
    }

// ---------------- precompute M = W1[:,1:129] @ W2, c = W1[:,1:129] @ b2 ----------------
__global__ void precompute_M(const float* __restrict__ W1,
                             const float* __restrict__ W2,
                             const float* __restrict__ b2)
{
    __shared__ float w1row[FIN];
    const int r = blockIdx.x;
    const int k = threadIdx.x;
    for (int j = k; j < FIN; j += blockDim.x) w1row[j] = W1[r * FIN + j];
    __syncthreads();
    float acc = 0.f;
#pragma unroll 8
    for (int i = 0; i < NSTATE; i++)
        acc = fmaf(w1row[1 + i], __ldg(&W2[i * HIDDEN + k]), acc);
    g_M[r * HIDDEN + k] = acc;
    if (k == 0) {
        float c = 0.f;
        for (int i = 0; i < NSTATE; i++) c = fmaf(w1row[1 + i], __ldg(&b2[i]), c);
        g_c[r] = c;
    }
}

// ---------------- precompute P[b][i][r] = Wu[r,:] . us[b][i][:] ----------------
__global__ void precompute_P(const float* __restrict__ W1,
                             const float* __restrict__ us)
{
    __shared__ float ush[64 * NINPUT];
    const int b = blockIdx.x;
    const int i0 = blockIdx.y * 64;
    const int r = threadIdx.x;
    float wu[NINPUT];
#pragma unroll
    for (int j = 0; j < NINPUT; j++) wu[j] = __ldg(&W1[r * FIN + 129 + j]);
    for (int idx = r; idx < 64 * NINPUT; idx += 256)
        ush[idx] = us[((size_t)b * KSTEPS + i0) * NINPUT + idx];
    __syncthreads();
    for (int ii = 0; ii < 64; ii++) {
        float acc = 0.f;
#pragma unroll
        for (int j = 0; j < NINPUT; j++) acc = fmaf(wu[j], ush[ii * NINPUT + j], acc);
        g_P[((size_t)b * KSTEPS + i0 + ii) * HIDDEN + r] = acc;
    }
}

// ---------------- main solver: 2-CTA cluster per trajectory ----------------
__global__ __launch_bounds__(512, 1) __cluster_dims__(2, 1, 1)
void ode_tsit5_kernel(const float* __restrict__ ts,
                      const float* __restrict__ y0,
                      const float* __restrict__ W1,
                      const float* __restrict__ b1,
                      const float* __restrict__ W2,
                      const float* __restrict__ b2,
                      float* __restrict__ out)
{
    const float TH[6] = {0.0f, 0.161f, 0.327f, 0.9f, 0.9800255409045097f, 1.0f};
    const float A[5][5] = {
        {0.161f, 0.f, 0.f, 0.f, 0.f},
        {-0.008480655492356989f, 0.335480655492357f, 0.f, 0.f, 0.f},
        {2.8971530571054935f, -6.359448489975075f, 4.3622954328695815f, 0.f, 0.f},
        {5.325864828439257f, -11.748883564062828f, 7.4955393428898365f, -0.09249506636175525f, 0.f},
        {5.86145544294642f, -12.92096931784711f, 8.159367898576159f, -0.071584973281401f, -0.028269050394068383f}
    };
    const float Bw[6] = {0.09646076681806523f, 0.01f, 0.4798896504144996f,
                         1.379008574103742f, -3.290069515436081f, 2.324710524099774f};

    extern __shared__ float sm[];
    float* Tb  = sm + OFF_TB;
    float* kp  = sm + OFF_KP;
    float* tss = sm + OFF_TSS;
    ulonglong2* w2u2 = (ulonglong2*)(sm + OFF_W2);

    const int t = threadIdx.x;
    const int b = blockIdx.x >> 1;                 // trajectory
    uint32_t rank;
    asm("mov.u32 %0, %%cluster_ctarank;" : "=r"(rank));
    const uint32_t prank = rank ^ 1u;

    const int rr = t >> 2;                         // local row 0..127
    const int r  = (int)rank * 128 + rr;           // global pre-activation row 0..255
    const int q  = t & 3;                          // quarter of K=256: T[q*64 .. q*64+64)
    const int il = t & 63;                         // W2-phase output (local)
    const int seg = t >> 6;                        // W2-phase K segment 0..7

    // ---- cluster addresses ----
    const uint32_t sm_base   = smem_u32(sm);
    const uint32_t mb_local  = sm_base + OFF_MB * 4;
    const uint32_t mb_remote = mapa_u32(mb_local, prank);
    const uint32_t rtp0 = mapa_u32(sm_base + OFF_TP0 * 4, prank);
    const uint32_t rtp1 = mapa_u32(sm_base + OFF_TP1 * 4, prank);
    const uint32_t rtb  = mapa_u32(sm_base + OFF_TB  * 4, prank);
    const uint32_t woff = (uint32_t)(((r >> 6) * 72 + (r & 63)) * 4);  // writer byte offset

    // ---- mbarrier init ----
    if (t == 0)
        asm volatile("mbarrier.init.shared.b64 [%0], %1;" :: "r"(mb_local), "r"(1u) : "memory");

    // ---- M quarter-row fully in registers: M[r][q*64 + 0..63] = 32 u64 ----
    unsigned long long mreg[32];
    {
        const unsigned long long* gm =
            (const unsigned long long*)&g_M[r * HIDDEN + q * 64];
#pragma unroll
        for (int m = 0; m < 32; m++) mreg[m] = gm[m];
    }
    const float creg = g_c[r];
    const float w1t  = __ldg(&W1[r * FIN]);
    const float b2r  = (t < 64) ? __ldg(&b2[rank * 64 + t]) : 0.0f;

    // ---- this CTA's 64 W2 rows, packed k-major ----
    {
        const float4* W2v = (const float4*)W2;     // [128][64] float4
        for (int idx = t; idx < 64 * 64; idx += 512) {
            int row = idx >> 6, j4 = idx & 63;
            float4 w = W2v[((int)rank * 64 + row) * 64 + j4];
            ulonglong2 pk; pk.x = pack2(w.x, w.y); pk.y = pack2(w.z, w.w);
            w2u2[j4 * 64 + row] = pk;
        }
    }
    if (t < KSTEPS) tss[t] = ts[t];

    // ---- beta = W1y[r,:] . y0 + b1[r] (quarter-split over 128 y-dims) ----
    float beta;
    {
        const float* w1p = W1 + r * FIN + 1 + q * 32;
        const float* yp  = y0 + b * NSTATE + q * 32;
        float acc = 0.f;
#pragma unroll 8
        for (int ii = 0; ii < 32; ii++) acc = fmaf(__ldg(&w1p[ii]), __ldg(&yp[ii]), acc);
        acc += __shfl_xor_sync(0xFFFFFFFFu, acc, 1);
        acc += __shfl_xor_sync(0xFFFFFFFFu, acc, 2);
        beta = acc + __ldg(&b1[r]);
    }

    // ---- y output state: this CTA owns 64 of the 128 outputs ----
    float yreg = 0.f;
    if (t < 64) {
        yreg = y0[b * NSTATE + (int)rank * 64 + t];
        out[(size_t)b * KSTEPS * NSTATE + (int)rank * 64 + t] = yreg;
    }

    // ---- P projections ----
    const float* gPb = g_P + (size_t)b * KSTEPS * HIDDEN + r;
    float P0    = __ldg(&gPb[0]);
    float P1    = __ldg(&gPb[HIDDEN]);
    float Pnext = __ldg(&gPb[2 * HIDDEN]);

    __syncthreads();
    // peer's mbar + smem must be ready before any remote traffic
    asm volatile("barrier.cluster.arrive.aligned;" ::: "memory");
    asm volatile("barrier.cluster.wait.aligned;" ::: "memory");

    float Q1 = __fdividef(P1 - P0, tss[1] - tss[0]);
    float Q0 = Q1;
    float act = fmaf(w1t, tss[0], beta + P0);
    float Garr[5];
    uint32_t xph = 0;

    for (int step = 0; step < KSTEPS - 1; ++step) {
        const float t0   = tss[step];
        const float hcur = tss[step + 1] - t0;
        float Tbacc = 0.f, bGacc = 0.f;

#pragma unroll
        for (int s = 0; s < 6; s++) {
            const int buf = s & 1;
            float* Tloc = sm + (buf ? OFF_TP1 : OFF_TP0);
            const uint32_t rTp = buf ? rtp1 : rtp0;

            float T = tanh_fast(act);
            Tbacc = fmaf(Bw[s], T, Tbacc);
            if (q == 0) {                           // one writer per row
                Tloc[(r >> 6) * 72 + (r & 63)] = T; // local
                st_cluster_f32(rTp + woff, T);      // peer
            }
            XCHG_SIGNAL_WAIT();

            // ---- G = M[r,:] . T + c : quarter dot from registers, shfl-reduce ----
            float G;
            {
                const ulonglong2* Tq = (const ulonglong2*)(Tloc + q * 72);
                unsigned long long a0 = 0ull, a1 = 0ull, a2 = 0ull, a3 = 0ull;
#pragma unroll
                for (int m = 0; m < 8; m++) {
                    ulonglong2 z0 = Tq[2 * m], z1 = Tq[2 * m + 1];
                    a0 = ffma2(mreg[4 * m + 0], z0.x, a0);
                    a1 = ffma2(mreg[4 * m + 1], z0.y, a1);
                    a2 = ffma2(mreg[4 * m + 2], z1.x, a2);
                    a3 = ffma2(mreg[4 * m + 3], z1.y, a3);
                }
                float v = (lo32(a0) + hi32(a0)) + (lo32(a1) + hi32(a1))
                        + (lo32(a2) + hi32(a2)) + (lo32(a3) + hi32(a3));
                v += __shfl_xor_sync(0xFFFFFFFFu, v, 1);
                v += __shfl_xor_sync(0xFFFFFFFFu, v, 2);
                G = v + creg;
            }
            bGacc = fmaf(Bw[s], G, bGacc);
            if (s < 5) {
                Garr[s] = G;
                float th = TH[s + 1];
                float t2 = th * th, t3 = t2 * th;
                float h00 = 2.f * t3 - 3.f * t2 + 1.f;
                float h01 = -2.f * t3 + 3.f * t2;
                float h10 = t3 - 2.f * t2 + th;
                float h11 = t3 - t2;
                float herm = h00 * P0 + h01 * P1 + hcur * (h10 * Q0 + h11 * Q1);
                float asum = 0.f;
#pragma unroll
                for (int j = 0; j <= s; j++) asum = fmaf(A[s][j], Garr[j], asum);
                act = fmaf(w1t, fmaf(th, hcur, t0), beta + herm + hcur * asum);
            }
        }

        // ---- Tb exchange ----
        if (q == 0) {
            Tb[r] = Tbacc;
            st_cluster_f32(rtb + (uint32_t)(r * 4), Tbacc);
        }
        XCHG_SIGNAL_WAIT();

        // ---- W2(half) . Tb : 64 outputs x 8 K-segments ----
        {
            const ulonglong2* hq = (const ulonglong2*)(Tb + seg * 32);
            const ulonglong2* wp = w2u2 + seg * 8 * 64 + il;
            unsigned long long a0 = 0ull, a1 = 0ull;
#pragma unroll
            for (int m = 0; m < 8; m++) {
                ulonglong2 w = wp[m * 64];
                ulonglong2 h = hq[m];
                a0 = ffma2(w.x, h.x, a0);
                a1 = ffma2(w.y, h.y, a1);
            }
            kp[seg * 64 + il] = (lo32(a0) + hi32(a0)) + (lo32(a1) + hi32(a1));
        }
        __syncthreads();

        // ---- finalize ----
        if (t < 64) {
            float kv = 0.f;
#pragma unroll
            for (int s8 = 0; s8 < 8; s8++) kv += kp[s8 * 64 + t];
            yreg = fmaf(hcur, kv + b2r, yreg);       // sum(Bw) == 1
            out[((size_t)b * KSTEPS + step + 1) * NSTATE + (int)rank * 64 + t] = yreg;
        }
        beta = fmaf(hcur, bGacc, beta);
        P0 = P1; Q0 = Q1; P1 = Pnext;
        if (step + 2 < KSTEPS) {
            Q1 = __fdividef(P1 - P0, tss[step + 2] - tss[step + 1]);
            if (step + 3 < KSTEPS) Pnext = __ldg(&gPb[(size_t)(step + 3) * HIDDEN]);
        } else {
            Q1 = 0.f;
        }
        act = fmaf(w1t, tss[step + 1], beta + P0);
    }

    // no CTA may exit while peer traffic could be in flight
    asm volatile("barrier.cluster.arrive.aligned;" ::: "memory");
    asm volatile("barrier.cluster.wait.aligned;" ::: "memory");
}

extern "C" void kernel_launch(void* const* d_in, const int* in_sizes, int n_in,
                              void* d_out, int out_size)
{
    const float *ts = nullptr, *y0 = nullptr, *us = nullptr;
    const float *W1 = nullptr, *b1 = nullptr, *W2 = nullptr, *b2 = nullptr;
    for (int i = 0; i < n_in; i++) {
        switch (in_sizes[i]) {
            case 512:      ts = (const float*)d_in[i]; break;
            case 8192:     y0 = (const float*)d_in[i]; break;
            case 1048576:  us = (const float*)d_in[i]; break;
            case 41216:    W1 = (const float*)d_in[i]; break;
            case 256:      b1 = (const float*)d_in[i]; break;
            case 32768:    W2 = (const float*)d_in[i]; break;
            case 128:      b2 = (const float*)d_in[i]; break;
            default: break;
        }
    }
    float* out = (float*)d_out;

    precompute_M<<<HIDDEN, HIDDEN>>>(W1, W2, b2);
    {
        dim3 g(BATCH, KSTEPS / 64);
        precompute_P<<<g, 256>>>(W1, us);
    }
    cudaFuncSetAttribute(ode_tsit5_kernel,
                         cudaFuncAttributeMaxDynamicSharedMemorySize, SMEM_BYTES);
    ode_tsit5_kernel<<<BATCH * 2, 512, SMEM_BYTES>>>(ts, y0, W1, b1, W2, b2, out);
}

// round 10
// speedup vs baseline: 1.5365x; 1.1190x over previous
#include <cuda_runtime.h>
#include <cstdint>
#include <math.h>

#define KSTEPS 512
#define BATCH  64
#define NSTATE 128
#define NINPUT 32
#define HIDDEN 256
#define FIN    161

// SMEM float offsets (per CTA)
#define OFF_W2  0        // 16640: w2q[(m*4+sub)*130 + i] u128 (k-split local half of W2)
#define OFF_TP0 16640    // 288: T buffer 0 (4 sections x [32 | 4pad | 32 | 4pad])
#define OFF_TP1 16928    // 288: T buffer 1
#define OFF_TBL 17216    // 128: Tb local half
#define OFF_KPO 17344    // 64:  own partial kv
#define OFF_KPR 17408    // 64:  peer partial kv (written remotely)
#define OFF_TSS 17472    // 512: time grid
#define OFF_MB  17984    // 5 mbarriers (u64 each): 4 stage + 1 kp
#define SMEM_FLOATS 18000
#define SMEM_BYTES  (SMEM_FLOATS * 4)

__device__ __align__(16) float g_M[HIDDEN * HIDDEN];          // M = W1y @ W2
__device__ float g_c[HIDDEN];                                  // c = W1y @ b2
__device__ float g_P[(size_t)BATCH * KSTEPS * HIDDEN];         // P[b][i][r] = Wu @ u_i

__device__ __forceinline__ unsigned long long ffma2(unsigned long long a,
                                                    unsigned long long b,
                                                    unsigned long long c) {
    unsigned long long d;
    asm("fma.rn.f32x2 %0, %1, %2, %3;" : "=l"(d) : "l"(a), "l"(b), "l"(c));
    return d;
}
__device__ __forceinline__ float lo32(unsigned long long v) { return __uint_as_float((unsigned)v); }
__device__ __forceinline__ float hi32(unsigned long long v) { return __uint_as_float((unsigned)(v >> 32)); }
__device__ __forceinline__ unsigned long long pack2(float a, float b) {
    return (unsigned long long)__float_as_uint(a) | ((unsigned long long)__float_as_uint(b) << 32);
}
__device__ __forceinline__ float tanh_fast(float x) {
    float y;
    asm("tanh.approx.f32 %0, %1;" : "=f"(y) : "f"(x));
    return y;
}
__device__ __forceinline__ uint32_t smem_u32(const void* p) {
    uint32_t a;
    asm("{ .reg .u64 tmp; cvta.to.shared.u64 tmp, %1; cvt.u32.u64 %0, tmp; }"
        : "=r"(a) : "l"(p));
    return a;
}
__device__ __forceinline__ uint32_t mapa_u32(uint32_t addr, uint32_t rank) {
    uint32_t r;
    asm("mapa.shared::cluster.u32 %0, %1, %2;" : "=r"(r) : "r"(addr), "r"(rank));
    return r;
}
__device__ __forceinline__ void st_cluster_f32(uint32_t addr, float v) {
    asm volatile("st.shared::cluster.f32 [%0], %1;" :: "r"(addr), "f"(v) : "memory");
}
__device__ __forceinline__ void arrive_remote_release(uint32_t addr) {
    asm volatile("mbarrier.arrive.release.cluster.shared::cluster.b64 _, [%0];"
                 :: "r"(addr) : "memory");
}
__device__ __forceinline__ void mbar_init(uint32_t addr, uint32_t cnt) {
    asm volatile("mbarrier.init.shared.b64 [%0], %1;" :: "r"(addr), "r"(cnt) : "memory");
}

#define WAIT_MBAR(addr, ph) do {                                                 \
    uint32_t _d;                                                                 \
    asm volatile("{\n\t.reg .pred p;\n\t"                                        \
        "mbarrier.try_wait.parity.acquire.cluster.shared::cta.b64 p, [%1], %2;\n\t" \
        "selp.b32 %0, 1, 0, p;\n\t}"                                             \
        : "=r"(_d) : "r"(addr), "r"(ph) : "memory");                             \
    while (!_d) {                                                                \
        asm volatile("{\n\t.reg .pred p;\n\t"                                    \
            "mbarrier.try_wait.parity.acquire.cluster.shared::cta.b64 p, [%1], %2, 0x989680;\n\t" \
            "selp.b32 %0, 1, 0, p;\n\t}"                                         \
            : "=r"(_d) : "r"(addr), "r"(ph) : "memory");                         \
    }                                                                            \
} while (0)

// ---------------- precompute M = W1[:,1:129] @ W2, c = W1[:,1:129] @ b2 ----------------
__global__ void precompute_M(const float* __restrict__ W1,
                             const float* __restrict__ W2,
                             const float* __restrict__ b2)
{
    __shared__ float w1row[FIN];
    const int r = blockIdx.x;
    const int k = threadIdx.x;
    for (int j = k; j < FIN; j += blockDim.x) w1row[j] = W1[r * FIN + j];
    __syncthreads();
    float acc = 0.f;
#pragma unroll 8
    for (int i = 0; i < NSTATE; i++)
        acc = fmaf(w1row[1 + i], __ldg(&W2[i * HIDDEN + k]), acc);
    g_M[r * HIDDEN + k] = acc;
    if (k == 0) {
        float c = 0.f;
        for (int i = 0; i < NSTATE; i++) c = fmaf(w1row[1 + i], __ldg(&b2[i]), c);
        g_c[r] = c;
    }
}

// ---------------- precompute P[b][i][r] = Wu[r,:] . us[b][i][:] ----------------
__global__ void precompute_P(const float* __restrict__ W1,
                             const float* __restrict__ us)
{
    __shared__ float ush[64 * NINPUT];
    const int b = blockIdx.x;
    const int i0 = blockIdx.y * 64;
    const int r = threadIdx.x;
    float wu[NINPUT];
#pragma unroll
    for (int j = 0; j < NINPUT; j++) wu[j] = __ldg(&W1[r * FIN + 129 + j]);
    for (int idx = r; idx < 64 * NINPUT; idx += 256)
        ush[idx] = us[((size_t)b * KSTEPS + i0) * NINPUT + idx];
    __syncthreads();
    for (int ii = 0; ii < 64; ii++) {
        float acc = 0.f;
#pragma unroll
        for (int j = 0; j < NINPUT; j++) acc = fmaf(wu[j], ush[ii * NINPUT + j], acc);
        g_P[((size_t)b * KSTEPS + i0 + ii) * HIDDEN + r] = acc;
    }
}

// ---------------- main solver: 2-CTA cluster per trajectory, fence-free exchange ----------------
__global__ __launch_bounds__(512, 1) __cluster_dims__(2, 1, 1)
void ode_tsit5_kernel(const float* __restrict__ ts,
                      const float* __restrict__ y0,
                      const float* __restrict__ W1,
                      const float* __restrict__ b1,
                      const float* __restrict__ W2,
                      const float* __restrict__ b2,
                      float* __restrict__ out)
{
    const float TH[6] = {0.0f, 0.161f, 0.327f, 0.9f, 0.9800255409045097f, 1.0f};
    const float A[5][5] = {
        {0.161f, 0.f, 0.f, 0.f, 0.f},
        {-0.008480655492356989f, 0.335480655492357f, 0.f, 0.f, 0.f},
        {2.8971530571054935f, -6.359448489975075f, 4.3622954328695815f, 0.f, 0.f},
        {5.325864828439257f, -11.748883564062828f, 7.4955393428898365f, -0.09249506636175525f, 0.f},
        {5.86145544294642f, -12.92096931784711f, 8.159367898576159f, -0.071584973281401f, -0.028269050394068383f}
    };
    const float Bw[6] = {0.09646076681806523f, 0.01f, 0.4798896504144996f,
                         1.379008574103742f, -3.290069515436081f, 2.324710524099774f};

    extern __shared__ float sm[];
    float* tbl = sm + OFF_TBL;
    float* kpo = sm + OFF_KPO;
    float* kpr = sm + OFF_KPR;
    float* tss = sm + OFF_TSS;

    const int t = threadIdx.x;
    const int b = blockIdx.x >> 1;
    uint32_t rank;
    asm("mov.u32 %0, %%cluster_ctarank;" : "=r"(rank));
    const uint32_t prank = rank ^ 1u;

    const int rr = t >> 2;                     // local row / W2 output index (0..127)
    const int rg = (int)rank * 128 + rr;       // global pre-activation row
    const int q  = t & 3;                      // k-chunk / W2 k-sub

    // ---- cluster addresses ----
    const uint32_t smb  = smem_u32(sm);
    const uint32_t mb_l = smb + OFF_MB * 4;
    const uint32_t mb_r = mapa_u32(mb_l, prank);
    const uint32_t rtp0 = mapa_u32(smb + OFF_TP0 * 4, prank);
    const uint32_t rtp1 = mapa_u32(smb + OFF_TP1 * 4, prank);
    const uint32_t rkpr = mapa_u32(smb + OFF_KPR * 4, prank);

    // T position for this row: section(64 rows) -> [32 | 4pad | 32 | 4pad]
    const int sec  = rg >> 6, tin = rg & 63;
    const int tpos = sec * 72 + (tin >> 5) * 36 + (tin & 31);
    const uint32_t wbyte = (uint32_t)tpos * 4;

    if (t == 0) {
#pragma unroll
        for (int m = 0; m < 4; m++) mbar_init(mb_l + m * 8, 128);
        mbar_init(mb_l + 32, 64);
    }

    // ---- M row split: 32 local-half elems + 32 remote-half elems in registers ----
    unsigned long long mregL[16], mregR[16];
    {
        const unsigned long long* gmL =
            (const unsigned long long*)&g_M[rg * HIDDEN + (int)rank * 128 + q * 32];
        const unsigned long long* gmR =
            (const unsigned long long*)&g_M[rg * HIDDEN + (int)prank * 128 + q * 32];
#pragma unroll
        for (int m = 0; m < 16; m++) { mregL[m] = gmL[m]; mregR[m] = gmR[m]; }
    }
    const float creg = g_c[rg];
    const float w1t  = __ldg(&W1[rg * FIN]);
    const float b2r  = (t < 64) ? __ldg(&b2[rank * 64 + t]) : 0.0f;

    // ---- local k-half of W2: w2q[(m4)*130 + i] = W2[i][rank*128 + 4*m4 .. +3] ----
    {
        const float4* W2v = (const float4*)W2;   // [128][64] float4
        ulonglong2* w2q = (ulonglong2*)(sm + OFF_W2);
        for (int idx = t; idx < 128 * 32; idx += 512) {
            int j4 = idx & 31, ii = idx >> 5;
            float4 w = W2v[ii * 64 + (int)rank * 32 + j4];
            ulonglong2 pk; pk.x = pack2(w.x, w.y); pk.y = pack2(w.z, w.w);
            w2q[j4 * 130 + ii] = pk;
        }
    }
    if (t < KSTEPS) tss[t] = ts[t];

    // ---- beta = W1y[rg,:] . y0 + b1[rg] ----
    float beta;
    {
        const float* w1p = W1 + rg * FIN + 1 + q * 32;
        const float* yp  = y0 + b * NSTATE + q * 32;
        float acc = 0.f;
#pragma unroll 8
        for (int ii = 0; ii < 32; ii++) acc = fmaf(__ldg(&w1p[ii]), __ldg(&yp[ii]), acc);
        acc += __shfl_xor_sync(0xFFFFFFFFu, acc, 1);
        acc += __shfl_xor_sync(0xFFFFFFFFu, acc, 2);
        beta = acc + __ldg(&b1[rg]);
    }

    // ---- y output state (64 outputs per CTA) ----
    float yreg = 0.f;
    if (t < 64) {
        yreg = y0[b * NSTATE + (int)rank * 64 + t];
        out[(size_t)b * KSTEPS * NSTATE + (int)rank * 64 + t] = yreg;
    }

    // ---- P projections ----
    const float* gPb = g_P + (size_t)b * KSTEPS * HIDDEN + rg;
    float P0    = __ldg(&gPb[0]);
    float P1    = __ldg(&gPb[HIDDEN]);
    float Pnext = __ldg(&gPb[2 * HIDDEN]);

    __syncthreads();
    asm volatile("barrier.cluster.arrive.aligned;" ::: "memory");
    asm volatile("barrier.cluster.wait.aligned;" ::: "memory");

    float Q1 = __fdividef(P1 - P0, tss[1] - tss[0]);
    float Q0 = Q1;
    float act = fmaf(w1t, tss[0], beta + P0);
    float Garr[5];
    uint32_t es = 0;   // stage-exchange counter

    // dot chunk offsets (floats)
    const int offL = (2 * (int)rank  + (q >> 1)) * 72 + (q & 1) * 36;
    const int offR = (2 * (int)prank + (q >> 1)) * 72 + (q & 1) * 36;

    for (int step = 0; step < KSTEPS - 1; ++step) {
        const float t0   = tss[step];
        const float hcur = tss[step + 1] - t0;
        float Tbacc = 0.f, bGacc = 0.f;

#pragma unroll
        for (int s = 0; s < 6; s++) {
            const uint32_t eidx = es & 3u;
            const uint32_t eph  = (es >> 2) & 1u;
            es++;
            float* Tb_ = sm + ((s & 1) ? OFF_TP1 : OFF_TP0);
            const uint32_t rT = (s & 1) ? rtp1 : rtp0;

            float T = tanh_fast(act);
            Tbacc = fmaf(Bw[s], T, Tbacc);
            if (q == 0) {                                  // one writer per row
                Tb_[tpos] = T;                             // local copy
                st_cluster_f32(rT + wbyte, T);             // push to peer
                arrive_remote_release(mb_r + eidx * 8);    // signal peer (release)
            }
            __syncthreads();

            // ---- local-half chunk dot (no peer dependency) ----
            unsigned long long a0 = 0ull, a1 = 0ull, a2 = 0ull, a3 = 0ull;
            {
                const ulonglong2* TqL = (const ulonglong2*)(Tb_ + offL);
#pragma unroll
                for (int m = 0; m < 4; m++) {
                    ulonglong2 z0 = TqL[2 * m], z1 = TqL[2 * m + 1];
                    a0 = ffma2(mregL[4 * m + 0], z0.x, a0);
                    a1 = ffma2(mregL[4 * m + 1], z0.y, a1);
                    a2 = ffma2(mregL[4 * m + 2], z1.x, a2);
                    a3 = ffma2(mregL[4 * m + 3], z1.y, a3);
                }
            }
            // ---- wait for peer half, then remote chunk ----
            WAIT_MBAR(mb_l + eidx * 8, eph);
            {
                const ulonglong2* TqR = (const ulonglong2*)(Tb_ + offR);
#pragma unroll
                for (int m = 0; m < 4; m++) {
                    ulonglong2 z0 = TqR[2 * m], z1 = TqR[2 * m + 1];
                    a0 = ffma2(mregR[4 * m + 0], z0.x, a0);
                    a1 = ffma2(mregR[4 * m + 1], z0.y, a1);
                    a2 = ffma2(mregR[4 * m + 2], z1.x, a2);
                    a3 = ffma2(mregR[4 * m + 3], z1.y, a3);
                }
            }
            float v = (lo32(a0) + hi32(a0)) + (lo32(a1) + hi32(a1))
                    + (lo32(a2) + hi32(a2)) + (lo32(a3) + hi32(a3));
            v += __shfl_xor_sync(0xFFFFFFFFu, v, 1);
            v += __shfl_xor_sync(0xFFFFFFFFu, v, 2);
            float G = v + creg;

            bGacc = fmaf(Bw[s], G, bGacc);
            if (s < 5) {
                Garr[s] = G;
                float th = TH[s + 1];
                float t2 = th * th, t3 = t2 * th;
                float h00 = 2.f * t3 - 3.f * t2 + 1.f;
                float h01 = -2.f * t3 + 3.f * t2;
                float h10 = t3 - 2.f * t2 + th;
                float h11 = t3 - t2;
                float herm = h00 * P0 + h01 * P1 + hcur * (h10 * Q0 + h11 * Q1);
                float asum = 0.f;
#pragma unroll
                for (int j = 0; j <= s; j++) asum = fmaf(A[s][j], Garr[j], asum);
                act = fmaf(w1t, fmaf(th, hcur, t0), beta + herm + hcur * asum);
            }
        }

        // ---- W2 phase: k-split, no pre-dot exchange ----
        if (q == 0) tbl[rr] = Tbacc;                       // local Tb half
        __syncthreads();
        {
            const ulonglong2* hq  = (const ulonglong2*)tbl;
            const ulonglong2* w2q = (const ulonglong2*)(sm + OFF_W2);
            unsigned long long a0 = 0ull, a1 = 0ull;
#pragma unroll
            for (int m = 0; m < 8; m++) {
                int j4 = m * 4 + q;
                ulonglong2 w = w2q[j4 * 130 + rr];
                ulonglong2 h = hq[j4];
                a0 = ffma2(w.x, h.x, a0);
                a1 = ffma2(w.y, h.y, a1);
            }
            float v = (lo32(a0) + hi32(a0)) + (lo32(a1) + hi32(a1));
            v += __shfl_xor_sync(0xFFFFFFFFu, v, 1);
            v += __shfl_xor_sync(0xFFFFFFFFu, v, 2);
            if (q == 0) {
                if ((rr >> 6) == (int)rank) {
                    kpo[rr & 63] = v;                      // my output, keep
                } else {
                    st_cluster_f32(rkpr + (uint32_t)(rr & 63) * 4, v);   // peer's output
                    arrive_remote_release(mb_r + 32);
                }
            }
        }
        __syncthreads();

        // ---- finalize y (warps 0-1 only wait) ----
        if (t < 64) {
            WAIT_MBAR(mb_l + 32, (uint32_t)(step & 1));
            float kv = kpo[t] + kpr[t];
            yreg = fmaf(hcur, kv + b2r, yreg);             // sum(Bw) == 1
            out[((size_t)b * KSTEPS + step + 1) * NSTATE + (int)rank * 64 + t] = yreg;
        }

        // ---- rotate beta / P / Q ----
        beta = fmaf(hcur, bGacc, beta);
        P0 = P1; Q0 = Q1; P1 = Pnext;
        if (step + 2 < KSTEPS) {
            Q1 = __fdividef(P1 - P0, tss[step + 2] - tss[step + 1]);
            if (step + 3 < KSTEPS) Pnext = __ldg(&gPb[(size_t)(step + 3) * HIDDEN]);
        } else {
            Q1 = 0.f;
        }
        act = fmaf(w1t, tss[step + 1], beta + P0);
    }

    asm volatile("barrier.cluster.arrive.aligned;" ::: "memory");
    asm volatile("barrier.cluster.wait.aligned;" ::: "memory");
}

extern "C" void kernel_launch(void* const* d_in, const int* in_sizes, int n_in,
                              void* d_out, int out_size)
{
    const float *ts = nullptr, *y0 = nullptr, *us = nullptr;
    const float *W1 = nullptr, *b1 = nullptr, *W2 = nullptr, *b2 = nullptr;
    for (int i = 0; i < n_in; i++) {
        switch (in_sizes[i]) {
            case 512:      ts = (const float*)d_in[i]; break;
            case 8192:     y0 = (const float*)d_in[i]; break;
            case 1048576:  us = (const float*)d_in[i]; break;
            case 41216:    W1 = (const float*)d_in[i]; break;
            case 256:      b1 = (const float*)d_in[i]; break;
            case 32768:    W2 = (const float*)d_in[i]; break;
            case 128:      b2 = (const float*)d_in[i]; break;
            default: break;
        }
    }
    float* out = (float*)d_out;

    precompute_M<<<HIDDEN, HIDDEN>>>(W1, W2, b2);
    {
        dim3 g(BATCH, KSTEPS / 64);
        precompute_P<<<g, 256>>>(W1, us);
    }
    cudaFuncSetAttribute(ode_tsit5_kernel,
                         cudaFuncAttributeMaxDynamicSharedMemorySize, SMEM_BYTES);
    ode_tsit5_kernel<<<BATCH * 2, 512, SMEM_BYTES>>>(ts, y0, W1, b1, W2, b2, out);
}

// round 11
// speedup vs baseline: 1.9198x; 1.2494x over previous
#include <cuda_runtime.h>
#include <cstdint>
#include <math.h>

#define KSTEPS 512
#define BATCH  64
#define NSTATE 128
#define NINPUT 32
#define HIDDEN 256
#define FIN    161

// SMEM float offsets (per CTA)
#define OFF_W2  0        // 16640: w2q[(m*4+sub)*130 + i] u128 (k-split local half of W2)
#define OFF_TP0 16640    // 288: T buffer 0 (4 sections x [32 | 4pad | 32 | 4pad])
#define OFF_TP1 16928    // 288: T buffer 1
#define OFF_TBL 17216    // 128: Tb local half
#define OFF_KPO 17344    // 64:  own partial kv
#define OFF_KPR 17408    // 64:  peer partial kv (written remotely via st.async)
#define OFF_TSS 17472    // 512: time grid
#define OFF_MB  17984    // 5 mbarriers (u64): 4 stage + 1 kp
#define SMEM_FLOATS 18000
#define SMEM_BYTES  (SMEM_FLOATS * 4)

__device__ __align__(16) float g_M[HIDDEN * HIDDEN];          // M = W1y @ W2
__device__ float g_c[HIDDEN];                                  // c = W1y @ b2
__device__ float g_P[(size_t)BATCH * KSTEPS * HIDDEN];         // P[b][i][r] = Wu @ u_i

__device__ __forceinline__ unsigned long long ffma2(unsigned long long a,
                                                    unsigned long long b,
                                                    unsigned long long c) {
    unsigned long long d;
    asm("fma.rn.f32x2 %0, %1, %2, %3;" : "=l"(d) : "l"(a), "l"(b), "l"(c));
    return d;
}
__device__ __forceinline__ float lo32(unsigned long long v) { return __uint_as_float((unsigned)v); }
__device__ __forceinline__ float hi32(unsigned long long v) { return __uint_as_float((unsigned)(v >> 32)); }
__device__ __forceinline__ unsigned long long pack2(float a, float b) {
    return (unsigned long long)__float_as_uint(a) | ((unsigned long long)__float_as_uint(b) << 32);
}
__device__ __forceinline__ float tanh_fast(float x) {
    float y;
    asm("tanh.approx.f32 %0, %1;" : "=f"(y) : "f"(x));
    return y;
}
__device__ __forceinline__ uint32_t smem_u32(const void* p) {
    uint32_t a;
    asm("{ .reg .u64 tmp; cvta.to.shared.u64 tmp, %1; cvt.u32.u64 %0, tmp; }"
        : "=r"(a) : "l"(p));
    return a;
}
__device__ __forceinline__ uint32_t mapa_u32(uint32_t addr, uint32_t rank) {
    uint32_t r;
    asm("mapa.shared::cluster.u32 %0, %1, %2;" : "=r"(r) : "r"(addr), "r"(rank));
    return r;
}
// store to remote smem, completion counted as tx bytes on the remote mbarrier
__device__ __forceinline__ void st_async_f32(uint32_t raddr, float v, uint32_t rmbar) {
    asm volatile("st.async.shared::cluster.mbarrier::complete_tx::bytes.f32 [%0], %1, [%2];"
                 :: "r"(raddr), "f"(v), "r"(rmbar) : "memory");
}
__device__ __forceinline__ void mbar_arm(uint32_t addr, uint32_t txbytes) {
    asm volatile("mbarrier.arrive.expect_tx.shared::cta.b64 _, [%0], %1;"
                 :: "r"(addr), "r"(txbytes) : "memory");
}
__device__ __forceinline__ void mbar_init(uint32_t addr, uint32_t cnt) {
    asm volatile("mbarrier.init.shared.b64 [%0], %1;" :: "r"(addr), "r"(cnt) : "memory");
}

#define WAIT_MBAR(addr, ph) do {                                                 \
    uint32_t _d;                                                                 \
    asm volatile("{\n\t.reg .pred p;\n\t"                                        \
        "mbarrier.try_wait.parity.acquire.cluster.shared::cta.b64 p, [%1], %2;\n\t" \
        "selp.b32 %0, 1, 0, p;\n\t}"                                             \
        : "=r"(_d) : "r"(addr), "r"(ph) : "memory");                             \
    while (!_d) {                                                                \
        asm volatile("{\n\t.reg .pred p;\n\t"                                    \
            "mbarrier.try_wait.parity.acquire.cluster.shared::cta.b64 p, [%1], %2, 0x989680;\n\t" \
            "selp.b32 %0, 1, 0, p;\n\t}"                                         \
            : "=r"(_d) : "r"(addr), "r"(ph) : "memory");                         \
    }                                                                            \
} while (0)

// ---------------- precompute M = W1[:,1:129] @ W2, c = W1[:,1:129] @ b2 ----------------
__global__ void precompute_M(const float* __restrict__ W1,
                             const float* __restrict__ W2,
                             const float* __restrict__ b2)
{
    __shared__ float w1row[FIN];
    const int r = blockIdx.x;
    const int k = threadIdx.x;
    for (int j = k; j < FIN; j += blockDim.x) w1row[j] = W1[r * FIN + j];
    __syncthreads();
    float acc = 0.f;
#pragma unroll 8
    for (int i = 0; i < NSTATE; i++)
        acc = fmaf(w1row[1 + i], __ldg(&W2[i * HIDDEN + k]), acc);
    g_M[r * HIDDEN + k] = acc;
    if (k == 0) {
        float c = 0.f;
        for (int i = 0; i < NSTATE; i++) c = fmaf(w1row[1 + i], __ldg(&b2[i]), c);
        g_c[r] = c;
    }
}

// ---------------- precompute P[b][i][r] = Wu[r,:] . us[b][i][:] ----------------
__global__ void precompute_P(const float* __restrict__ W1,
                             const float* __restrict__ us)
{
    __shared__ float ush[64 * NINPUT];
    const int b = blockIdx.x;
    const int i0 = blockIdx.y * 64;
    const int r = threadIdx.x;
    float wu[NINPUT];
#pragma unroll
    for (int j = 0; j < NINPUT; j++) wu[j] = __ldg(&W1[r * FIN + 129 + j]);
    for (int idx = r; idx < 64 * NINPUT; idx += 256)
        ush[idx] = us[((size_t)b * KSTEPS + i0) * NINPUT + idx];
    __syncthreads();
    for (int ii = 0; ii < 64; ii++) {
        float acc = 0.f;
#pragma unroll
        for (int j = 0; j < NINPUT; j++) acc = fmaf(wu[j], ush[ii * NINPUT + j], acc);
        g_P[((size_t)b * KSTEPS + i0 + ii) * HIDDEN + r] = acc;
    }
}

// ---------------- main solver: 2-CTA cluster per trajectory, tx-based exchange ----------------
__global__ __launch_bounds__(512, 1) __cluster_dims__(2, 1, 1)
void ode_tsit5_kernel(const float* __restrict__ ts,
                      const float* __restrict__ y0,
                      const float* __restrict__ W1,
                      const float* __restrict__ b1,
                      const float* __restrict__ W2,
                      const float* __restrict__ b2,
                      float* __restrict__ out)
{
    const float TH[6] = {0.0f, 0.161f, 0.327f, 0.9f, 0.9800255409045097f, 1.0f};
    const float A[5][5] = {
        {0.161f, 0.f, 0.f, 0.f, 0.f},
        {-0.008480655492356989f, 0.335480655492357f, 0.f, 0.f, 0.f},
        {2.8971530571054935f, -6.359448489975075f, 4.3622954328695815f, 0.f, 0.f},
        {5.325864828439257f, -11.748883564062828f, 7.4955393428898365f, -0.09249506636175525f, 0.f},
        {5.86145544294642f, -12.92096931784711f, 8.159367898576159f, -0.071584973281401f, -0.028269050394068383f}
    };
    const float Bw[6] = {0.09646076681806523f, 0.01f, 0.4798896504144996f,
                         1.379008574103742f, -3.290069515436081f, 2.324710524099774f};

    extern __shared__ float sm[];
    float* tbl = sm + OFF_TBL;
    float* kpo = sm + OFF_KPO;
    float* kpr = sm + OFF_KPR;
    float* tss = sm + OFF_TSS;

    const int t = threadIdx.x;
    const int b = blockIdx.x >> 1;
    uint32_t rank;
    asm("mov.u32 %0, %%cluster_ctarank;" : "=r"(rank));
    const uint32_t prank = rank ^ 1u;

    const int rr = t >> 2;                     // local row / W2 output index (0..127)
    const int rg = (int)rank * 128 + rr;       // global pre-activation row
    const int q  = t & 3;                      // k-chunk / W2 k-sub

    // ---- cluster addresses ----
    const uint32_t smb  = smem_u32(sm);
    const uint32_t mb_l = smb + OFF_MB * 4;
    const uint32_t mb_r = mapa_u32(mb_l, prank);
    const uint32_t rtp0 = mapa_u32(smb + OFF_TP0 * 4, prank);
    const uint32_t rtp1 = mapa_u32(smb + OFF_TP1 * 4, prank);
    const uint32_t rkpr = mapa_u32(smb + OFF_KPR * 4, prank);

    // T position for this row: section(64 rows) -> [32 | 4pad | 32 | 4pad]
    const int sec  = rg >> 6, tin = rg & 63;
    const int tpos = sec * 72 + (tin >> 5) * 36 + (tin & 31);
    const uint32_t wbyte = (uint32_t)tpos * 4;

    if (t == 0) {
#pragma unroll
        for (int m = 0; m < 4; m++) mbar_init(mb_l + m * 8, 1);   // armed via expect_tx
        mbar_init(mb_l + 32, 1);
    }

    // ---- M row split: 32 local-half + 32 remote-half elems in registers ----
    unsigned long long mregL[16], mregR[16];
    {
        const unsigned long long* gmL =
            (const unsigned long long*)&g_M[rg * HIDDEN + (int)rank * 128 + q * 32];
        const unsigned long long* gmR =
            (const unsigned long long*)&g_M[rg * HIDDEN + (int)prank * 128 + q * 32];
#pragma unroll
        for (int m = 0; m < 16; m++) { mregL[m] = gmL[m]; mregR[m] = gmR[m]; }
    }
    const float creg = g_c[rg];
    const float w1t  = __ldg(&W1[rg * FIN]);
    const float b2r  = (t < 64) ? __ldg(&b2[rank * 64 + t]) : 0.0f;

    // ---- local k-half of W2 ----
    {
        const float4* W2v = (const float4*)W2;   // [128][64] float4
        ulonglong2* w2q = (ulonglong2*)(sm + OFF_W2);
        for (int idx = t; idx < 128 * 32; idx += 512) {
            int j4 = idx & 31, ii = idx >> 5;
            float4 w = W2v[ii * 64 + (int)rank * 32 + j4];
            ulonglong2 pk; pk.x = pack2(w.x, w.y); pk.y = pack2(w.z, w.w);
            w2q[j4 * 130 + ii] = pk;
        }
    }
    if (t < KSTEPS) tss[t] = ts[t];

    // ---- beta = W1y[rg,:] . y0 + b1[rg] ----
    float beta;
    {
        const float* w1p = W1 + rg * FIN + 1 + q * 32;
        const float* yp  = y0 + b * NSTATE + q * 32;
        float acc = 0.f;
#pragma unroll 8
        for (int ii = 0; ii < 32; ii++) acc = fmaf(__ldg(&w1p[ii]), __ldg(&yp[ii]), acc);
        acc += __shfl_xor_sync(0xFFFFFFFFu, acc, 1);
        acc += __shfl_xor_sync(0xFFFFFFFFu, acc, 2);
        beta = acc + __ldg(&b1[rg]);
    }

    // ---- y output state (64 outputs per CTA) ----
    float yreg = 0.f;
    if (t < 64) {
        yreg = y0[b * NSTATE + (int)rank * 64 + t];
        out[(size_t)b * KSTEPS * NSTATE + (int)rank * 64 + t] = yreg;
    }

    // ---- P projections ----
    const float* gPb = g_P + (size_t)b * KSTEPS * HIDDEN + rg;
    float P0    = __ldg(&gPb[0]);
    float P1    = __ldg(&gPb[HIDDEN]);
    float Pnext = __ldg(&gPb[2 * HIDDEN]);

    __syncthreads();
    asm volatile("barrier.cluster.arrive.aligned;" ::: "memory");
    asm volatile("barrier.cluster.wait.aligned;" ::: "memory");

    float Q1 = __fdividef(P1 - P0, tss[1] - tss[0]);
    float Q0 = Q1;
    float act = fmaf(w1t, tss[0], beta + P0);
    float Garr[5];
    uint32_t es = 0;   // stage-exchange counter

    // dot chunk offsets (floats)
    const int offL = (2 * (int)rank  + (q >> 1)) * 72 + (q & 1) * 36;
    const int offR = (2 * (int)prank + (q >> 1)) * 72 + (q & 1) * 36;

    for (int step = 0; step < KSTEPS - 1; ++step) {
        const float t0   = tss[step];
        const float hcur = tss[step + 1] - t0;
        float Tbacc = 0.f, bGacc = 0.f;

#pragma unroll
        for (int s = 0; s < 6; s++) {
            const uint32_t eidx = es & 3u;
            const uint32_t eph  = (es >> 2) & 1u;
            es++;
            float* Tb_ = sm + ((s & 1) ? OFF_TP1 : OFF_TP0);
            const uint32_t rT = (s & 1) ? rtp1 : rtp0;

            float T = tanh_fast(act);
            Tbacc = fmaf(Bw[s], T, Tbacc);
            if (q == 0) {                                  // one writer per row
                Tb_[tpos] = T;                             // local copy (plain STS)
                st_async_f32(rT + wbyte, T, mb_r + eidx * 8);   // peer copy + tx
            }
            if (t == 0) mbar_arm(mb_l + eidx * 8, 512u);   // 128 peer stores x 4B
            __syncthreads();                               // local T visible

            // ---- local-half chunk dot (overlaps peer flight) ----
            unsigned long long a0 = 0ull, a1 = 0ull, a2 = 0ull, a3 = 0ull;
            {
                const ulonglong2* TqL = (const ulonglong2*)(Tb_ + offL);
#pragma unroll
                for (int m = 0; m < 4; m++) {
                    ulonglong2 z0 = TqL[2 * m], z1 = TqL[2 * m + 1];
                    a0 = ffma2(mregL[4 * m + 0], z0.x, a0);
                    a1 = ffma2(mregL[4 * m + 1], z0.y, a1);
                    a2 = ffma2(mregL[4 * m + 2], z1.x, a2);
                    a3 = ffma2(mregL[4 * m + 3], z1.y, a3);
                }
            }
            // ---- wait for peer half, then remote chunk ----
            WAIT_MBAR(mb_l + eidx * 8, eph);
            {
                const ulonglong2* TqR = (const ulonglong2*)(Tb_ + offR);
#pragma unroll
                for (int m = 0; m < 4; m++) {
                    ulonglong2 z0 = TqR[2 * m], z1 = TqR[2 * m + 1];
                    a0 = ffma2(mregR[4 * m + 0], z0.x, a0);
                    a1 = ffma2(mregR[4 * m + 1], z0.y, a1);
                    a2 = ffma2(mregR[4 * m + 2], z1.x, a2);
                    a3 = ffma2(mregR[4 * m + 3], z1.y, a3);
                }
            }
            float v = (lo32(a0) + hi32(a0)) + (lo32(a1) + hi32(a1))
                    + (lo32(a2) + hi32(a2)) + (lo32(a3) + hi32(a3));
            v += __shfl_xor_sync(0xFFFFFFFFu, v, 1);
            v += __shfl_xor_sync(0xFFFFFFFFu, v, 2);
            float G = v + creg;

            bGacc = fmaf(Bw[s], G, bGacc);
            if (s < 5) {
                Garr[s] = G;
                float th = TH[s + 1];
                float t2 = th * th, t3 = t2 * th;
                float h00 = 2.f * t3 - 3.f * t2 + 1.f;
                float h01 = -2.f * t3 + 3.f * t2;
                float h10 = t3 - 2.f * t2 + th;
                float h11 = t3 - t2;
                float herm = h00 * P0 + h01 * P1 + hcur * (h10 * Q0 + h11 * Q1);
                float asum = 0.f;
#pragma unroll
                for (int j = 0; j <= s; j++) asum = fmaf(A[s][j], Garr[j], asum);
                act = fmaf(w1t, fmaf(th, hcur, t0), beta + herm + hcur * asum);
            }
        }

        // ---- W2 phase: k-split, local Tb half only ----
        if (q == 0) tbl[rr] = Tbacc;
        if (t == 0) mbar_arm(mb_l + 32, 256u);             // 64 peer kp stores x 4B
        __syncthreads();
        {
            const ulonglong2* hq  = (const ulonglong2*)tbl;
            const ulonglong2* w2q = (const ulonglong2*)(sm + OFF_W2);
            unsigned long long a0 = 0ull, a1 = 0ull;
#pragma unroll
            for (int m = 0; m < 8; m++) {
                int j4 = m * 4 + q;
                ulonglong2 w = w2q[j4 * 130 + rr];
                ulonglong2 h = hq[j4];
                a0 = ffma2(w.x, h.x, a0);
                a1 = ffma2(w.y, h.y, a1);
            }
            float v = (lo32(a0) + hi32(a0)) + (lo32(a1) + hi32(a1));
            v += __shfl_xor_sync(0xFFFFFFFFu, v, 1);
            v += __shfl_xor_sync(0xFFFFFFFFu, v, 2);
            if (q == 0) {
                if ((rr >> 6) == (int)rank) {
                    kpo[rr & 63] = v;                      // my output, keep local
                } else {
                    st_async_f32(rkpr + (uint32_t)(rr & 63) * 4, v, mb_r + 32);
                }
            }
        }
        __syncthreads();                                   // kpo visible

        // ---- finalize y (warps 0-1 only wait) ----
        if (t < 64) {
            WAIT_MBAR(mb_l + 32, (uint32_t)(step & 1));
            float kv = kpo[t] + kpr[t];
            yreg = fmaf(hcur, kv + b2r, yreg);             // sum(Bw) == 1
            out[((size_t)b * KSTEPS + step + 1) * NSTATE + (int)rank * 64 + t] = yreg;
        }

        // ---- rotate beta / P / Q ----
        beta = fmaf(hcur, bGacc, beta);
        P0 = P1; Q0 = Q1; P1 = Pnext;
        if (step + 2 < KSTEPS) {
            Q1 = __fdividef(P1 - P0, tss[step + 2] - tss[step + 1]);
            if (step + 3 < KSTEPS) Pnext = __ldg(&gPb[(size_t)(step + 3) * HIDDEN]);
        } else {
            Q1 = 0.f;
        }
        act = fmaf(w1t, tss[step + 1], beta + P0);
    }

    asm volatile("barrier.cluster.arrive.aligned;" ::: "memory");
    asm volatile("barrier.cluster.wait.aligned;" ::: "memory");
}

extern "C" void kernel_launch(void* const* d_in, const int* in_sizes, int n_in,
                              void* d_out, int out_size)
{
    const float *ts = nullptr, *y0 = nullptr, *us = nullptr;
    const float *W1 = nullptr, *b1 = nullptr, *W2 = nullptr, *b2 = nullptr;
    for (int i = 0; i < n_in; i++) {
        switch (in_sizes[i]) {
            case 512:      ts = (const float*)d_in[i]; break;
            case 8192:     y0 = (const float*)d_in[i]; break;
            case 1048576:  us = (const float*)d_in[i]; break;
            case 41216:    W1 = (const float*)d_in[i]; break;
            case 256:      b1 = (const float*)d_in[i]; break;
            case 32768:    W2 = (const float*)d_in[i]; break;
            case 128:      b2 = (const float*)d_in[i]; break;
            default: break;
        }
    }
    float* out = (float*)d_out;

    precompute_M<<<HIDDEN, HIDDEN>>>(W1, W2, b2);
    {
        dim3 g(BATCH, KSTEPS / 64);
        precompute_P<<<g, 256>>>(W1, us);
    }
    cudaFuncSetAttribute(ode_tsit5_kernel,
                         cudaFuncAttributeMaxDynamicSharedMemorySize, SMEM_BYTES);
    ode_tsit5_kernel<<<BATCH * 2, 512, SMEM_BYTES>>>(ts, y0, W1, b1, W2, b2, out);
}